// round 13
// baseline (speedup 1.0000x reference)
#include <cuda_runtime.h>
#include <cstdint>

// WaveNet autoregressive decode, fully linearized:
//   - 8-layer dilated conv stack is affine -> effective kernel E[256][256] + bias
//   - encoder contributions c_i[b][ch] precomputed for all 32 steps
//   - HIDDEN-SPACE recursion: z_i = Z0_i + sum_m o_m * G[i-1-m], with
//     Z0 = c@W1 + b1 (one bulk GEMM) and G[r] = E[r]@W1 (tiny GEMM).
// R9: comp reads convs_w DIRECTLY (native [co][ci][k] layout -> each thread
//     streams a contiguous 512B row slice) instead of the transposed g_wT
//     (stride-1KB scatter, measured latency-bound at ~17us/layer).

#define DEC  32
#define NB   64
#define C    256
#define HID  512
#define TT   543
#define RF   256

__device__ float g_E[2][RF][C];        // [parity][tau][c] effective kernel
__device__ float g_bias[2][C];         // [parity][c]      effective bias
__device__ float g_c[DEC][NB][C];      // encoder contributions (feat space)
__device__ float g_G[DEC - 1][HID];    // G[r] = E[r] @ W1
__device__ float g_z[DEC][NB][HID];    // Z0 = c @ W1 + b1

// ---------------------------------------------------------------------------
// prep: init E from conv0 (Cin=1).
//   E[0][c] = w[c,0,1] (lag 0), E[1][c] = w[c,0,0] (lag 1), rest zero.
// ---------------------------------------------------------------------------
__global__ void prep_kernel(const float* __restrict__ c0w,
                            const float* __restrict__ c0b) {
    int tau = blockIdx.x, t = threadIdx.x;
    float v = 0.f;
    if (tau == 0)      v = c0w[2 * t + 1];
    else if (tau == 1) v = c0w[2 * t];
    g_E[0][tau][t] = v;
    if (tau == 0) g_bias[0][t] = c0b[t];
}

// ---------------------------------------------------------------------------
// comp: one layer of kernel composition.
//   Enew[tau][co] = sum_ci w1[co][ci]*Eold[tau][ci] + w0[co][ci]*Eold[tau-d][ci]
// Weights read straight from convs_w: row (L,co) is 512 contiguous floats
// (ci-major, k inner) -> 32 LDG.128 per thread, fully streamed.
// Layer L outputs NT = 4<<L live taps; rows NT..min(2NT,256)-1 zero-padded.
// Block = 4 taus x 128 co (co-half via blockIdx LSB), ci split 4-way across
// 512 threads, partials combined through smem.
// ---------------------------------------------------------------------------
__global__ void __launch_bounds__(512) comp_kernel(
    int L, int d, int NT, int sp,
    const float* __restrict__ cw, const float* __restrict__ lb) {
    int dp = sp ^ 1;
    int nblk = (int)gridDim.x - 1;
    if ((int)blockIdx.x == nblk) {            // bias recurrence block
        __shared__ float bsh[256];
        __shared__ float br[2][256];
        int tt = threadIdx.x & 255, s2 = threadIdx.x >> 8;   // co, ci-half
        if (threadIdx.x < 256) bsh[threadIdx.x] = g_bias[sp][threadIdx.x];
        __syncthreads();
        const float4* wr = (const float4*)(cw +
            (((size_t)L * C + tt) * C + s2 * 128) * 2);
        float acc = 0.f;
        #pragma unroll 8
        for (int q = 0; q < 64; q++) {        // 128 ci as 64 float4 (2 ci each)
            float4 w = wr[q];
            acc += (w.x + w.y) * bsh[s2 * 128 + 2 * q]
                 + (w.z + w.w) * bsh[s2 * 128 + 2 * q + 1];
        }
        br[s2][tt] = acc;
        __syncthreads();
        if (s2 == 0) g_bias[dp][tt] = lb[tt] + br[0][tt] + br[1][tt];
        return;
    }
    int tl = threadIdx.x & 127;
    int s  = threadIdx.x >> 7;                // 0..3  ci-quarter
    int tau0 = (int)(blockIdx.x >> 1) * 4;
    int co  = ((blockIdx.x & 1) << 7) + tl;
    if (tau0 >= NT) {                          // zero-pad rows NT..2NT-1
        g_E[dp][tau0 + s][co] = 0.f;
        return;
    }
    __shared__ alignas(16) float A[4][C], B[4][C];
    __shared__ float red[4][4][128];
    for (int r = threadIdx.x; r < 1024; r += 512) {
        int u = r >> 8, c = r & 255;
        A[u][c] = g_E[sp][tau0 + u][c];
        int tm = tau0 + u - d;
        B[u][c] = (tm >= 0) ? g_E[sp][tm][c] : 0.f;
    }
    __syncthreads();
    float acc[4] = {0.f, 0.f, 0.f, 0.f};
    int ci0 = s * 64;
    // contiguous weight row slice for (L, co, ci0..ci0+63): 128 floats
    const float4* wrow = (const float4*)(cw +
        (((size_t)L * C + co) * C + ci0) * 2);
    #pragma unroll 4
    for (int q = 0; q < 16; q++) {             // 4 ci per iteration
        float4 wa = wrow[2 * q];               // ci: +0 (w0,w1), +1 (w0,w1)
        float4 wb = wrow[2 * q + 1];           // ci: +2, +3
        int ci = ci0 + 4 * q;
        #pragma unroll
        for (int u = 0; u < 4; u++) {
            float4 a  = *(const float4*)&A[u][ci];
            float4 bb = *(const float4*)&B[u][ci];
            acc[u] += a.x * wa.y + bb.x * wa.x
                    + a.y * wa.w + bb.y * wa.z
                    + a.z * wb.y + bb.z * wb.x
                    + a.w * wb.w + bb.w * wb.z;
        }
    }
    #pragma unroll
    for (int u = 0; u < 4; u++) red[s][u][tl] = acc[u];
    __syncthreads();
    if (s == 0) {
        #pragma unroll
        for (int u = 0; u < 4; u++)
            g_E[dp][tau0 + u][co] =
                red[0][u][tl] + red[1][u][tl] + red[2][u][tl] + red[3][u][tl];
    }
}

// ---------------------------------------------------------------------------
// c: encoder contributions (feat space).
//   c[i][b][c] = b_eff[c] + sum_{tau=i..255} E[tau][c] * x[b][511+i-tau]
// ---------------------------------------------------------------------------
__global__ void c_kernel(const float* __restrict__ x) {
    int b = blockIdx.x >> 1, half = blockIdx.x & 1;
    int t = threadIdx.x;
    int c = half * 128 + t;
    __shared__ float xs[256];
    const float* xb = x + b * TT;
    for (int k = t; k < 256; k += 128) xs[k] = xb[256 + k];
    __syncthreads();
    float acc[DEC];
    float bv = g_bias[1][c];
    #pragma unroll
    for (int i = 0; i < DEC; i++) acc[i] = bv;
    for (int tau = 0; tau < 32; tau++) {
        float e = g_E[1][tau][c];
        for (int i = 0; i <= tau; i++)
            acc[i] += e * xs[255 + i - tau];
    }
    for (int tau = 32; tau < RF; tau++) {
        float e = g_E[1][tau][c];
        const float* xp = &xs[255 - tau];
        #pragma unroll
        for (int i = 0; i < DEC; i++)
            acc[i] += e * xp[i];
    }
    #pragma unroll
    for (int i = 0; i < DEC; i++) g_c[i][b][c] = acc[i];
}

// ---------------------------------------------------------------------------
// g: G[r][h] = sum_c E[1][r][c] * W1[c][h], r in 0..30.
// grid 124 = 31 r x 4 h-quarters; block 128.
// ---------------------------------------------------------------------------
__global__ void g_kernel(const float* __restrict__ w1) {
    int r = blockIdx.x >> 2, hq = blockIdx.x & 3;
    int h = hq * 128 + threadIdx.x;
    float acc = 0.f;
    const float* ep = &g_E[1][r][0];
    #pragma unroll 8
    for (int c = 0; c < C; c++)
        acc += ep[c] * w1[(size_t)c * HID + h];
    g_G[r][h] = acc;
}

// ---------------------------------------------------------------------------
// z0: bulk GEMM  Z0[row][h] = g_c_flat[row][:] @ W1[:, h] + b1[h]
// rows = (i,b) flattened: 2048 x 256 @ 256 x 512.
// grid (32, 4): 64-row x 128-col tiles; block 256; thread tile 8M x 4N.
// ---------------------------------------------------------------------------
__global__ void __launch_bounds__(256) z0_kernel(
    const float* __restrict__ w1, const float* __restrict__ b1) {
    __shared__ alignas(16) float As[32][68];   // [k][m], padded (68%32=4)
    __shared__ alignas(16) float Bs[32][128];  // [k][n]
    int t  = threadIdx.x;
    int tx = t & 31;            // n-group: cols tx*4 .. tx*4+3
    int ty = t >> 5;            // m-group: rows ty*8 .. ty*8+7
    int row0 = blockIdx.x * 64;
    int col0 = blockIdx.y * 128;
    const float* gc = &g_c[0][0][0];           // flat [2048][256]
    float acc[8][4];
    #pragma unroll
    for (int m = 0; m < 8; m++)
        #pragma unroll
        for (int n = 0; n < 4; n++) acc[m][n] = 0.f;

    for (int kk = 0; kk < 256; kk += 32) {
        #pragma unroll
        for (int u = 0; u < 8; u++) {          // A: 64m x 32k
            int idx = u * 256 + t;
            int m = idx >> 5, k = idx & 31;
            As[k][m] = gc[(size_t)(row0 + m) * C + kk + k];
        }
        #pragma unroll
        for (int u = 0; u < 16; u++) {         // B: 32k x 128n
            int idx = u * 256 + t;
            int k = idx >> 7, n = idx & 127;
            Bs[k][n] = w1[(size_t)(kk + k) * HID + col0 + n];
        }
        __syncthreads();
        #pragma unroll
        for (int k = 0; k < 32; k++) {
            float4 bv = *(const float4*)&Bs[k][tx * 4];
            float4 a0 = *(const float4*)&As[k][ty * 8];
            float4 a1 = *(const float4*)&As[k][ty * 8 + 4];
            float am[8] = {a0.x, a0.y, a0.z, a0.w, a1.x, a1.y, a1.z, a1.w};
            float bn[4] = {bv.x, bv.y, bv.z, bv.w};
            #pragma unroll
            for (int m = 0; m < 8; m++)
                #pragma unroll
                for (int n = 0; n < 4; n++)
                    acc[m][n] += am[m] * bn[n];
        }
        __syncthreads();
    }
    float* gz = &g_z[0][0][0];                 // flat [2048][512]
    float b1v[4];
    #pragma unroll
    for (int n = 0; n < 4; n++) b1v[n] = b1[col0 + tx * 4 + n];
    #pragma unroll
    for (int m = 0; m < 8; m++) {
        float4 o = make_float4(acc[m][0] + b1v[0], acc[m][1] + b1v[1],
                               acc[m][2] + b1v[2], acc[m][3] + b1v[3]);
        *(float4*)&gz[(size_t)(row0 + ty * 8 + m) * HID + col0 + tx * 4] = o;
    }
}

// ---------------------------------------------------------------------------
// decode: one CTA per batch, 512 threads, thread t owns hidden unit t.
// z[32] and G[31] live in REGISTERS; per step: relu dot w2, block-reduce
// (shfl + double-buffered warp partials -> single __syncthreads), every
// thread redundantly sums the 16 partials, then <=31 register FFMAs feed o
// into future z's. No cross-CTA sync anywhere.
// ---------------------------------------------------------------------------
__global__ void __launch_bounds__(512) decode_kernel(
    const float* __restrict__ w2, const float* __restrict__ b2,
    float* __restrict__ out) {
    int b = blockIdx.x, t = threadIdx.x;
    __shared__ float wpart[2][16];
    float z[DEC], G[DEC - 1];
    #pragma unroll
    for (int i = 0; i < DEC; i++) z[i] = g_z[i][b][t];
    #pragma unroll
    for (int r = 0; r < DEC - 1; r++) G[r] = g_G[r][t];
    float w2v = w2[t], b2v = b2[0];
    int warp = t >> 5, lane = t & 31;

    #pragma unroll
    for (int i = 0; i < DEC; i++) {
        float p = fmaxf(z[i], 0.f) * w2v;
        #pragma unroll
        for (int off = 16; off > 0; off >>= 1)
            p += __shfl_down_sync(0xffffffffu, p, off);
        if (lane == 0) wpart[i & 1][warp] = p;
        __syncthreads();
        float o = b2v;
        #pragma unroll
        for (int w = 0; w < 16; w++) o += wpart[i & 1][w];
        if (t == 0) out[b * DEC + i] = o;
        #pragma unroll
        for (int ip = i + 1; ip < DEC; ip++)
            z[ip] += o * G[ip - 1 - i];
    }
}

// ---------------------------------------------------------------------------
extern "C" void kernel_launch(void* const* d_in, const int* in_sizes, int n_in,
                              void* d_out, int out_size) {
    const float* inputs = (const float*)d_in[0];
    const float* c0w    = (const float*)d_in[1];
    const float* c0b    = (const float*)d_in[2];
    const float* cw     = (const float*)d_in[3];
    const float* cb     = (const float*)d_in[4];
    const float* w1     = (const float*)d_in[5];
    const float* b1     = (const float*)d_in[6];
    const float* w2     = (const float*)d_in[7];
    const float* b2     = (const float*)d_in[8];
    // d_in[9] = teacher_forcing_ratio (always 0) -- unused.

    prep_kernel<<<256, 256>>>(c0w, c0b);
    int sp = 0;
    for (int L = 0; L < 7; L++) {
        int NT  = 4 << L;
        int NTz = (2 * NT < 256) ? 2 * NT : 256;
        int grid = (NTz / 4) * 2 + 1;
        comp_kernel<<<grid, 512>>>(L, 2 << L, NT, sp, cw, cb + L * C);
        sp ^= 1;
    }
    // final E / bias in parity 1 (7 flips from parity 0)
    c_kernel<<<128, 128>>>(inputs);
    g_kernel<<<(DEC - 1) * 4, 128>>>(w1);
    dim3 zgrid(32, 4);
    z0_kernel<<<zgrid, 256>>>(w1, b1);
    decode_kernel<<<NB, 512>>>(w2, b2, (float*)d_out);
}

// round 17
// speedup vs baseline: 2.0757x; 2.0757x over previous
#include <cuda_runtime.h>
#include <cstdint>

// WaveNet decode, fully linearized AND fully fused into ONE kernel.
// Evidence (R1/R8/R13): each dependent micro-launch costs ~15-20us regardless
// of inner-loop shape; 12 serial launches dominate runtime. This version runs
// all phases in a single 129-CTA single-wave kernel with a software grid
// barrier (residency guaranteed: 129 CTAs <= 148 SMs at 1 CTA/SM).
// Math (unchanged, proven to 6e-7): conv stack is affine -> effective kernel
// E + bias; c_i = encoder contributions; z_i = Z0_i + sum o_m*G[i-1-m];
// Z0 = c@W1+b1; G[r] = E[r]@W1; decode loop is register-resident per batch.

#define DEC  32
#define NB   64
#define C    256
#define HID  512
#define TT   543
#define RF   256
#define NCTA 129

__device__ float g_E[2][RF][C];        // [parity][tau][c] effective kernel
__device__ float g_bias[2][C];         // [parity][c]
__device__ float g_wT[7][2][C][C];     // [layer][k][ci][co] transposed weights
__device__ float g_c[DEC][NB][C];      // encoder contributions
__device__ float g_G[DEC - 1][HID];    // E[r] @ W1
__device__ float g_z[DEC][NB][HID];    // c @ W1 + b1

__device__ unsigned g_barcnt = 0;
__device__ volatile unsigned g_bargen = 0;

// Sense-reversing grid barrier. Safe: all NCTA CTAs are resident (single
// wave), so every arriver eventually spins-free. Gen read precedes arrive
// (fenced) so a releaser's flip can't strand a late reader.
__device__ __forceinline__ void gridbar() {
    __syncthreads();
    if (threadIdx.x == 0) {
        __threadfence();
        unsigned g = g_bargen;
        __threadfence();
        if (atomicAdd(&g_barcnt, 1u) == NCTA - 1) {
            atomicExch(&g_barcnt, 0u);
            __threadfence();
            g_bargen = g + 1;
        } else {
            while (g_bargen == g) { __nanosleep(32); }
        }
        __threadfence();
    }
    __syncthreads();
}

__global__ void __launch_bounds__(512, 1) mega_kernel(
    const float* __restrict__ inputs,
    const float* __restrict__ c0w, const float* __restrict__ c0b,
    const float* __restrict__ cw,  const float* __restrict__ cb,
    const float* __restrict__ w1,  const float* __restrict__ b1,
    const float* __restrict__ w2,  const float* __restrict__ b2,
    float* __restrict__ out) {
    __shared__ __align__(16) unsigned char sm[26 * 1024];
    int cta = blockIdx.x, t = threadIdx.x;

    // ---------------- phase 0: prep E/bias + weight transpose ----------------
    if (cta < 128) {                       // E parity-0 init (all 256 taus)
        int tau = cta * 2 + (t >> 8), c2 = t & 255;
        float v = 0.f;
        if (tau == 0)      v = c0w[2 * c2 + 1];
        else if (tau == 1) v = c0w[2 * c2];
        g_E[0][tau][c2] = v;
    }
    if (cta == 128 && t < 256) g_bias[0][t] = c0b[t];
    // transpose convs_w -> g_wT: 1792 (layer,co) units over 129 CTAs x 2 halves
    for (int u = cta + NCTA * (t >> 8); u < 1792; u += 2 * NCTA) {
        int j = u >> 8, co = u & 255, ci = t & 255;
        float2 w = reinterpret_cast<const float2*>(cw)[((size_t)(j * C + co)) * C + ci];
        g_wT[j][0][ci][co] = w.x;
        g_wT[j][1][ci][co] = w.y;
    }
    gridbar();

    // ---------------- phases 1..7: kernel composition ----------------
    int sp = 0;
    for (int L = 0; L < 7; L++) {
        int d = 2 << L, NT = 4 << L;
        int NTz = (2 * NT < 256) ? 2 * NT : 256;
        int nblk = (NTz / 4) * 2;
        int dp = sp ^ 1;
        if (cta < nblk) {
            int tl = t & 127, s = t >> 7;       // s: ci-quarter
            int tau0 = (cta >> 1) * 4;
            int co = ((cta & 1) << 7) + tl;
            if (tau0 >= NT) {                    // zero-pad rows NT..2NT-1
                g_E[dp][tau0 + s][co] = 0.f;
            } else {
                float (*A)[C]   = (float(*)[C])(sm);
                float (*B)[C]   = (float(*)[C])(sm + 4096);
                float (*red)[4][128] = (float(*)[4][128])(sm + 8192);
                for (int r = t; r < 1024; r += 512) {
                    int u = r >> 8, c2 = r & 255;
                    A[u][c2] = g_E[sp][tau0 + u][c2];
                    int tm = tau0 + u - d;
                    B[u][c2] = (tm >= 0) ? g_E[sp][tm][c2] : 0.f;
                }
                __syncthreads();
                float acc[4] = {0.f, 0.f, 0.f, 0.f};
                const float* w0p = &g_wT[L][0][0][co];
                const float* w1p = &g_wT[L][1][0][co];
                int ci0 = s * 64;
                #pragma unroll 4
                for (int q = 0; q < 16; q++) {
                    int ci = ci0 + 4 * q;
                    float w1v[4], w0v[4];
                    #pragma unroll
                    for (int j = 0; j < 4; j++) {
                        w1v[j] = w1p[(size_t)(ci + j) * C];
                        w0v[j] = w0p[(size_t)(ci + j) * C];
                    }
                    #pragma unroll
                    for (int u = 0; u < 4; u++) {
                        float4 a  = *(const float4*)&A[u][ci];
                        float4 bb = *(const float4*)&B[u][ci];
                        acc[u] += a.x * w1v[0] + a.y * w1v[1] + a.z * w1v[2] + a.w * w1v[3]
                                + bb.x * w0v[0] + bb.y * w0v[1] + bb.z * w0v[2] + bb.w * w0v[3];
                    }
                }
                #pragma unroll
                for (int u = 0; u < 4; u++) red[s][u][tl] = acc[u];
                __syncthreads();
                if (s == 0) {
                    #pragma unroll
                    for (int u = 0; u < 4; u++)
                        g_E[dp][tau0 + u][co] =
                            red[0][u][tl] + red[1][u][tl] + red[2][u][tl] + red[3][u][tl];
                }
            }
        } else if (cta == 128) {                 // bias recurrence
            float* br = (float*)(sm);            // [2][256]
            int tt = t & 255, s2 = t >> 8;
            const float* lb = cb + L * C;
            const float* w0 = &g_wT[L][0][0][tt];
            const float* w1p = &g_wT[L][1][0][tt];
            float acc = 0.f;
            for (int ci = 128 * s2; ci < 128 * s2 + 128; ci++)
                acc += (w0[ci * C] + w1p[ci * C]) * g_bias[sp][ci];
            br[s2 * 256 + tt] = acc;
            __syncthreads();
            if (s2 == 0) g_bias[dp][tt] = lb[tt] + br[tt] + br[256 + tt];
        }
        sp = dp;
        gridbar();
    }
    // final E / bias live in parity 1 (sp == 1 now)

    // ---------------- phase 8: encoder contributions c  +  G = E@W1 ----------
    if (cta < 64) {                              // c: one batch per CTA
        float* xs = (float*)sm;                  // [256]
        int b = cta;
        for (int k2 = t; k2 < 256; k2 += 512) xs[k2] = inputs[b * TT + 256 + k2];
        __syncthreads();
        int c2 = t & 255, ib = (t >> 8) * 16;    // this thread: i in [ib, ib+16)
        float acc[16];
        float bv = g_bias[1][c2];
        #pragma unroll
        for (int ii = 0; ii < 16; ii++) acc[ii] = bv;
        for (int tau = ib; tau < ib + 16; tau++) {   // triangular: i <= tau
            float e = g_E[1][tau][c2];
            for (int ii = 0; ii <= tau - ib; ii++)
                acc[ii] += e * xs[255 + ib + ii - tau];
        }
        for (int tau = ib + 16; tau < RF; tau++) {   // full 16-wide
            float e = g_E[1][tau][c2];
            const float* xp = &xs[255 + ib - tau];
            #pragma unroll
            for (int ii = 0; ii < 16; ii++)
                acc[ii] += e * xp[ii];
        }
        #pragma unroll
        for (int ii = 0; ii < 16; ii++) g_c[ib + ii][b][c2] = acc[ii];
    } else if (cta >= 64 && cta < 64 + DEC - 1) { // G rows, one r per CTA
        int r = cta - 64;                         // 0..30
        float a = 0.f;
        const float* ep = &g_E[1][r][0];
        #pragma unroll 8
        for (int c2 = 0; c2 < C; c2++)
            a += ep[c2] * w1[(size_t)c2 * HID + t];
        g_G[r][t] = a;
    }
    gridbar();

    // ---------------- phase 9: z0 GEMM (2048x256 @ 256x512 + b1) -------------
    if (cta < 128) {
        float (*As)[68]  = (float(*)[68])(sm);          // [32][68]
        float (*Bs)[128] = (float(*)[128])(sm + 8704);  // [32][128]
        int tx = t & 31, ty = t >> 5;                   // ty 0..15
        int row0 = (cta >> 2) * 64;
        int col0 = (cta & 3) * 128;
        const float* gc = &g_c[0][0][0];                // flat [2048][256]
        float acc[4][4];
        #pragma unroll
        for (int m = 0; m < 4; m++)
            #pragma unroll
            for (int n = 0; n < 4; n++) acc[m][n] = 0.f;
        for (int kk = 0; kk < 256; kk += 32) {
            #pragma unroll
            for (int u = 0; u < 4; u++) {               // A: 64m x 32k
                int idx = u * 512 + t;
                int m = idx >> 5, k = idx & 31;
                As[k][m] = gc[(size_t)(row0 + m) * C + kk + k];
            }
            #pragma unroll
            for (int u = 0; u < 8; u++) {               // B: 32k x 128n
                int idx = u * 512 + t;
                int k = idx >> 7, n = idx & 127;
                Bs[k][n] = w1[(size_t)(kk + k) * HID + col0 + n];
            }
            __syncthreads();
            #pragma unroll
            for (int k = 0; k < 32; k++) {
                float4 bv = *(const float4*)&Bs[k][tx * 4];
                float4 av = *(const float4*)&As[k][ty * 4];
                float am[4] = {av.x, av.y, av.z, av.w};
                float bn[4] = {bv.x, bv.y, bv.z, bv.w};
                #pragma unroll
                for (int m = 0; m < 4; m++)
                    #pragma unroll
                    for (int n = 0; n < 4; n++)
                        acc[m][n] += am[m] * bn[n];
            }
            __syncthreads();
        }
        float* gz = &g_z[0][0][0];                      // flat [2048][512]
        float b1v[4];
        #pragma unroll
        for (int n = 0; n < 4; n++) b1v[n] = b1[col0 + tx * 4 + n];
        #pragma unroll
        for (int m = 0; m < 4; m++) {
            float4 o = make_float4(acc[m][0] + b1v[0], acc[m][1] + b1v[1],
                                   acc[m][2] + b1v[2], acc[m][3] + b1v[3]);
            *(float4*)&gz[(size_t)(row0 + ty * 4 + m) * HID + col0 + tx * 4] = o;
        }
    }
    gridbar();   // LAST barrier — all CTAs participate, then non-decode exit

    // ---------------- phase 10: autoregressive decode ----------------
    if (cta >= NB) return;
    {
        float* wpart = (float*)sm;                       // [2][16]
        int b = cta;
        float z[DEC], G[DEC - 1];
        #pragma unroll
        for (int i = 0; i < DEC; i++) z[i] = g_z[i][b][t];
        #pragma unroll
        for (int r = 0; r < DEC - 1; r++) G[r] = g_G[r][t];
        float w2v = w2[t], b2v = b2[0];
        int warp = t >> 5, lane = t & 31;
        #pragma unroll
        for (int i = 0; i < DEC; i++) {
            float p = fmaxf(z[i], 0.f) * w2v;
            #pragma unroll
            for (int off = 16; off > 0; off >>= 1)
                p += __shfl_down_sync(0xffffffffu, p, off);
            if (lane == 0) wpart[(i & 1) * 16 + warp] = p;
            __syncthreads();
            float o = b2v;
            #pragma unroll
            for (int w = 0; w < 16; w++) o += wpart[(i & 1) * 16 + w];
            if (t == 0) out[b * DEC + i] = o;
            #pragma unroll
            for (int ip = i + 1; ip < DEC; ip++)
                z[ip] += o * G[ip - 1 - i];
        }
    }
}

// ---------------------------------------------------------------------------
extern "C" void kernel_launch(void* const* d_in, const int* in_sizes, int n_in,
                              void* d_out, int out_size) {
    const float* inputs = (const float*)d_in[0];
    const float* c0w    = (const float*)d_in[1];
    const float* c0b    = (const float*)d_in[2];
    const float* cw     = (const float*)d_in[3];
    const float* cb     = (const float*)d_in[4];
    const float* w1     = (const float*)d_in[5];
    const float* b1     = (const float*)d_in[6];
    const float* w2     = (const float*)d_in[7];
    const float* b2     = (const float*)d_in[8];
    // d_in[9] = teacher_forcing_ratio (always 0) -- unused.

    mega_kernel<<<NCTA, 512>>>(inputs, c0w, c0b, cw, cb, w1, b1, w2, b2,
                               (float*)d_out);
}